// round 1
// baseline (speedup 1.0000x reference)
#include <cuda_runtime.h>
#include <cstdint>

#define BB 8
#define SS 8192
#define DD 512
#define NTOK (BB * SS)

// Scratch (allocation-free per harness rules)
__device__ int g_cs_pos[NTOK];
__device__ int g_first_ce[BB];

// ---------------------------------------------------------------------------
// Kernel 1: per-row cummax of CODE_START positions + first CODE_END index.
// One block per batch row, 1024 threads, 8 contiguous elems per thread.
// ---------------------------------------------------------------------------
__global__ void __launch_bounds__(1024) nvm_scan_kernel(const int* __restrict__ tok) {
    int b = blockIdx.x;
    const int* row = tok + b * SS;
    __shared__ int part[1024];
    __shared__ int ce_min;
    int tid = threadIdx.x;
    if (tid == 0) ce_min = SS;
    __syncthreads();

    int base = tid * 8;
    int vals[8];
    int run = -1;
    int lce = SS;
#pragma unroll
    for (int i = 0; i < 8; i++) {
        int t = row[base + i];
        if (t == 256) run = base + i;          // CODE_START
        vals[i] = run;
        if (t == 257 && (base + i) < lce) lce = base + i;  // CODE_END
    }
    part[tid] = run;
    if (lce < SS) atomicMin(&ce_min, lce);
    __syncthreads();

    // Hillis-Steele inclusive max-scan over 1024 thread partials
    for (int off = 1; off < 1024; off <<= 1) {
        int other = (tid >= off) ? part[tid - off] : -1;
        __syncthreads();
        if (other > part[tid]) part[tid] = other;
        __syncthreads();
    }
    int prefix = (tid == 0) ? -1 : part[tid - 1];
#pragma unroll
    for (int i = 0; i < 8; i++)
        g_cs_pos[b * SS + base + i] = (vals[i] > prefix) ? vals[i] : prefix;
    if (tid == 0) g_first_ce[b] = ce_min;
}

// ---------------------------------------------------------------------------
// Kernel 2: embedding gather + feature overwrites.
// blockDim = (128, 4): 128 lanes cover 512 dims as float4; 4 tokens/block.
// Lane 0 of each token group computes the 48-bit onehot mask + flag bits.
// ---------------------------------------------------------------------------
__global__ void __launch_bounds__(512) nvm_embed_kernel(
    const float4* __restrict__ tbl4,     // [272 * 128] float4
    const int* __restrict__ tok,         // [B*S]
    float4* __restrict__ out4)           // [B*S * 128] float4
{
    __shared__ unsigned long long sh_m[4];
    __shared__ unsigned int sh_f[4];

    int tid  = threadIdx.x;              // 0..127 (dim lane)
    int slot = threadIdx.y;              // 0..3   (token slot)
    int gtok = blockIdx.x * 4 + slot;    // global token index
    int b = gtok >> 13;
    int s = gtok & (SS - 1);

    int t = __ldg(&tok[gtok]);

    if (tid == 0) {
        unsigned long long m = 0ull;
        unsigned int f = 0u;
        if (t == 259) f |= 1u;                       // THINK_START -> dim 456
        if (t == 260) f |= 2u;                       // THINK_END   -> dim 457
        if (t == 258 && (s + 8) < SS) f |= 4u;       // MEM_EXEC    -> dim 458

        // code path
        int cs  = g_cs_pos[gtok];
        int fce = g_first_ce[b];
        if (cs >= 0 && s < fce && t < 256) {
            int seq = s - cs - 1;
            int bo  = seq & 7;
            if (seq >= 0 && bo < 5) {
                int addr = (((seq >> 3) << 3) + 2 + bo) & 4095;
                m |= (1ull << (addr & 15))
                   | (1ull << (16 + ((addr >> 4) & 15)))
                   | (1ull << (32 + ((addr >> 8) & 15)));
            }
        }
        // mem look-back path: offsets 0..3, source position s-5-off
        const int* row = tok + b * SS;
#pragma unroll
        for (int off = 0; off < 4; off++) {
            int i = s - 5 - off;
            if (i >= 0 && (i + 8) < SS && row[i] == 258) {
                int a = ((row[i + 1] | (row[i + 2] << 8)) + off) & 4095;
                m |= (1ull << (a & 15))
                   | (1ull << (16 + ((a >> 4) & 15)))
                   | (1ull << (32 + ((a >> 8) & 15)));
            }
        }
        sh_m[slot] = m;
        sh_f[slot] = f;
    }

    // table row load overlaps with lane-0 mask work
    float4 v = __ldg(&tbl4[t * 128 + tid]);
    __syncthreads();

    int d0 = tid << 2;
    if (d0 >= 204 && d0 < 256) {
        // dims [206, 254): ADDR_KEY onehot region
        unsigned long long m = sh_m[slot];
        float* vp = reinterpret_cast<float*>(&v);
#pragma unroll
        for (int c = 0; c < 4; c++) {
            int d = d0 + c;
            if (d >= 206 && d < 254 && ((m >> (d - 206)) & 1ull)) vp[c] = 1.0f;
        }
    } else if (d0 == 456) {
        unsigned int f = sh_f[slot];
        if (f & 1u) v.x = 1.0f;  // 456 MARK_TS
        if (f & 2u) v.y = 1.0f;  // 457 MARK_TE
        if (f & 4u) v.z = 1.0f;  // 458 MEM_EXEC
    }

    __stcs(&out4[(size_t)gtok * 128 + tid], v);
}

// ---------------------------------------------------------------------------
extern "C" void kernel_launch(void* const* d_in, const int* in_sizes, int n_in,
                              void* d_out, int out_size) {
    // metadata order: embed_table [272*512] f32, token_ids [8*8192] i32.
    // Defensive: identify by element count.
    const float* tbl;
    const int* tok;
    if (in_sizes[0] == 272 * 512) {
        tbl = (const float*)d_in[0];
        tok = (const int*)d_in[1];
    } else {
        tbl = (const float*)d_in[1];
        tok = (const int*)d_in[0];
    }
    float* out = (float*)d_out;

    nvm_scan_kernel<<<BB, 1024>>>(tok);

    dim3 blk(128, 4);
    nvm_embed_kernel<<<NTOK / 4, blk>>>(
        (const float4*)tbl, tok, (float4*)out);
}

// round 2
// speedup vs baseline: 1.3469x; 1.3469x over previous
#include <cuda_runtime.h>
#include <cstdint>

#define BB 8
#define SS 8192
#define NTOK (BB * SS)

// Per-token packed info: bits[0:48) = addr onehot, bit48=TS, bit49=TE, bit50=MEM_EXEC
__device__ unsigned long long g_mask[NTOK];

// ---------------------------------------------------------------------------
// Kernel 1: per-row scan (cummax of CODE_START, first CODE_END) + full
// per-token mask computation. One block per batch row, 1024 threads,
// 8 contiguous tokens per thread.
// ---------------------------------------------------------------------------
__global__ void __launch_bounds__(1024) nvm_scan_kernel(const int* __restrict__ tok) {
    int b = blockIdx.x;
    const int* row = tok + b * SS;
    __shared__ int part[1024];
    __shared__ int ce_min;
    int tid = threadIdx.x;
    if (tid == 0) ce_min = SS;
    __syncthreads();

    int base = tid * 8;
    int tv[8];
    int vals[8];
    int run = -1;
    int lce = SS;
#pragma unroll
    for (int i = 0; i < 8; i++) {
        int t = row[base + i];
        tv[i] = t;
        if (t == 256) run = base + i;                        // CODE_START
        vals[i] = run;
        if (t == 257 && (base + i) < lce) lce = base + i;    // CODE_END
    }
    part[tid] = run;
    if (lce < SS) atomicMin(&ce_min, lce);
    __syncthreads();

    // Hillis-Steele inclusive max-scan over 1024 thread partials
    for (int off = 1; off < 1024; off <<= 1) {
        int other = (tid >= off) ? part[tid - off] : -1;
        __syncthreads();
        if (other > part[tid]) part[tid] = other;
        __syncthreads();
    }
    int prefix = (tid == 0) ? -1 : part[tid - 1];
    int fce = ce_min;   // safe: all atomicMin happened before first barrier

#pragma unroll
    for (int i = 0; i < 8; i++) {
        int s = base + i;
        int t = tv[i];
        int cs = (vals[i] > prefix) ? vals[i] : prefix;

        unsigned long long m = 0ull;
        if (t == 259) m |= (1ull << 48);                     // THINK_START
        if (t == 260) m |= (1ull << 49);                     // THINK_END
        if (t == 258 && (s + 8) < SS) m |= (1ull << 50);     // MEM_EXEC

        // code path
        if (cs >= 0 && s < fce && t < 256) {
            int seq = s - cs - 1;
            int bo  = seq & 7;
            if (seq >= 0 && bo < 5) {
                int addr = (((seq >> 3) << 3) + 2 + bo) & 4095;
                m |= (1ull << (addr & 15))
                   | (1ull << (16 + ((addr >> 4) & 15)))
                   | (1ull << (32 + ((addr >> 8) & 15)));
            }
        }
        // mem look-back path: offsets 0..3, source position s-5-off
#pragma unroll
        for (int off = 0; off < 4; off++) {
            int j = s - 5 - off;
            if (j >= 0 && (j + 8) < SS && row[j] == 258) {
                int a = ((row[j + 1] | (row[j + 2] << 8)) + off) & 4095;
                m |= (1ull << (a & 15))
                   | (1ull << (16 + ((a >> 4) & 15)))
                   | (1ull << (32 + ((a >> 8) & 15)));
            }
        }
        g_mask[b * SS + s] = m;
    }
}

// ---------------------------------------------------------------------------
// Kernel 2: pure streaming gather + masked overwrite. No shared, no sync.
// blockDim (128,4); each thread handles 2 consecutive tokens (MLP=2).
// ---------------------------------------------------------------------------
__device__ __forceinline__ void apply_mask(float4& v, unsigned long long m, int tid) {
    int d0 = tid << 2;
    if (tid >= 51 && tid <= 63) {
        float* vp = reinterpret_cast<float*>(&v);
#pragma unroll
        for (int c = 0; c < 4; c++) {
            int d = d0 + c;
            if (d >= 206 && d < 254 && ((m >> (d - 206)) & 1ull)) vp[c] = 1.0f;
        }
    } else if (tid == 114) {
        if ((m >> 48) & 1ull) v.x = 1.0f;   // dim 456
        if ((m >> 49) & 1ull) v.y = 1.0f;   // dim 457
        if ((m >> 50) & 1ull) v.z = 1.0f;   // dim 458
    }
}

__global__ void __launch_bounds__(512) nvm_embed_kernel(
    const float4* __restrict__ tbl4,                 // [272 * 128]
    const int* __restrict__ tok,                     // [B*S]
    float4* __restrict__ out4)                       // [B*S * 128]
{
    int tid  = threadIdx.x;                          // 0..127 (dim lane)
    int slot = threadIdx.y;                          // 0..3
    int gtok0 = blockIdx.x * 8 + slot * 2;           // two consecutive tokens
    int gtok1 = gtok0 + 1;

    int t0 = __ldg(&tok[gtok0]);
    int t1 = __ldg(&tok[gtok1]);
    unsigned long long m0 = __ldg(&g_mask[gtok0]);
    unsigned long long m1 = __ldg(&g_mask[gtok1]);

    float4 v0 = __ldg(&tbl4[t0 * 128 + tid]);
    float4 v1 = __ldg(&tbl4[t1 * 128 + tid]);

    apply_mask(v0, m0, tid);
    apply_mask(v1, m1, tid);

    __stcs(&out4[(size_t)gtok0 * 128 + tid], v0);
    __stcs(&out4[(size_t)gtok1 * 128 + tid], v1);
}

// ---------------------------------------------------------------------------
extern "C" void kernel_launch(void* const* d_in, const int* in_sizes, int n_in,
                              void* d_out, int out_size) {
    const float* tbl;
    const int* tok;
    if (in_sizes[0] == 272 * 512) {
        tbl = (const float*)d_in[0];
        tok = (const int*)d_in[1];
    } else {
        tbl = (const float*)d_in[1];
        tok = (const int*)d_in[0];
    }
    float* out = (float*)d_out;

    nvm_scan_kernel<<<BB, 1024>>>(tok);

    dim3 blk(128, 4);
    nvm_embed_kernel<<<NTOK / 8, blk>>>(
        (const float4*)tbl, tok, (float4*)out);
}

// round 3
// speedup vs baseline: 1.5112x; 1.1220x over previous
#include <cuda_runtime.h>
#include <cstdint>

#define BB 8
#define SS 8192
#define NTOK (BB * SS)

typedef unsigned long long u64;

// Per-token packed word:
//   bits [0,48)  : addr one-hot (lo/hi/top nibbles)
//   bit 48       : THINK_START  -> dim 456
//   bit 49       : THINK_END    -> dim 457
//   bit 50       : MEM_EXEC     -> dim 458
//   bits [52,61) : token id (0..271)
__device__ u64 g_mask[NTOK];

// ---------------------------------------------------------------------------
// Kernel 1: per-row scan + full per-token mask computation.
// One block per batch row, 1024 threads, 8 contiguous tokens per thread.
// Row staged in shared; look-back window held in registers; shuffle scan.
// ---------------------------------------------------------------------------
__global__ void __launch_bounds__(1024) nvm_scan_kernel(const int* __restrict__ tok) {
    __shared__ int sh[SS];           // 32 KB
    __shared__ int warp_part[32];
    __shared__ int ce_sh;

    int b = blockIdx.x;
    int tid = threadIdx.x;
    int lane = tid & 31;
    int wid = tid >> 5;

    if (tid == 0) ce_sh = SS;

    // coalesced staging of the row (2 iterations of int4)
    const int4* row4 = reinterpret_cast<const int4*>(tok + b * SS);
    int4* sh4 = reinterpret_cast<int4*>(sh);
#pragma unroll
    for (int i = tid; i < SS / 4; i += 1024) sh4[i] = row4[i];
    __syncthreads();

    int base = tid * 8;

    // win[0..7] = predecessor thread's 8 tokens, win[8..15] = own 8 tokens
    int win[16];
    {
        int4 a, c;
        if (tid > 0) {
            a = sh4[tid * 2 - 2];
            c = sh4[tid * 2 - 1];
        } else {
            a = make_int4(0, 0, 0, 0);
            c = a;
        }
        win[0] = a.x; win[1] = a.y; win[2] = a.z; win[3] = a.w;
        win[4] = c.x; win[5] = c.y; win[6] = c.z; win[7] = c.w;
        int4 d = sh4[tid * 2];
        int4 e = sh4[tid * 2 + 1];
        win[8]  = d.x; win[9]  = d.y; win[10] = d.z; win[11] = d.w;
        win[12] = e.x; win[13] = e.y; win[14] = e.z; win[15] = e.w;
    }

    // local cummax of CODE_START position + local first CODE_END
    int vals[8];
    int run = -1, lce = SS;
#pragma unroll
    for (int i = 0; i < 8; i++) {
        int t = win[8 + i];
        if (t == 256) run = base + i;
        vals[i] = run;
        if (t == 257 && (base + i) < lce) lce = base + i;
    }
    if (lce < SS) atomicMin(&ce_sh, lce);

    // warp-shuffle inclusive max-scan of per-thread `run`
    int v = run;
#pragma unroll
    for (int off = 1; off < 32; off <<= 1) {
        int o = __shfl_up_sync(0xffffffffu, v, off);
        if (lane >= off && o > v) v = o;
    }
    if (lane == 31) warp_part[wid] = v;
    __syncthreads();
    if (wid == 0) {
        int w = warp_part[lane];
#pragma unroll
        for (int off = 1; off < 32; off <<= 1) {
            int o = __shfl_up_sync(0xffffffffu, w, off);
            if (lane >= off && o > w) w = o;
        }
        warp_part[lane] = w;
    }
    __syncthreads();

    int warp_prefix = (wid == 0) ? -1 : warp_part[wid - 1];
    int excl_in_warp = __shfl_up_sync(0xffffffffu, v, 1);
    if (lane == 0) excl_in_warp = -1;
    int prefix = (excl_in_warp > warp_prefix) ? excl_in_warp : warp_prefix;
    int fce = ce_sh;

    u64 out[8];
#pragma unroll
    for (int i = 0; i < 8; i++) {
        int s = base + i;
        int t = win[8 + i];
        int cs = (vals[i] > prefix) ? vals[i] : prefix;

        u64 m = ((u64)t) << 52;
        if (t == 259) m |= (1ull << 48);
        if (t == 260) m |= (1ull << 49);
        if (t == 258 && (s + 8) < SS) m |= (1ull << 50);

        // code path
        if (cs >= 0 && s < fce && t < 256) {
            int seq = s - cs - 1;
            int bo  = seq & 7;
            if (seq >= 0 && bo < 5) {
                int addr = (((seq >> 3) << 3) + 2 + bo) & 4095;
                m |= (1ull << (addr & 15))
                   | (1ull << (16 + ((addr >> 4) & 15)))
                   | (1ull << (32 + ((addr >> 8) & 15)));
            }
        }
        // mem look-back: source position j = s - 5 - off, entirely in `win`
#pragma unroll
        for (int off = 0; off < 4; off++) {
            int jg = s - 5 - off;                  // global source position
            int ji = i + 3 - off;                  // window index (= jg - base + 8)
            if (jg >= 0 && (jg + 8) < SS && win[ji + 8 - 8 + 0 + (0)] == win[ji] && win[ji] == 258) {
                int a = ((win[ji + 1] | (win[ji + 2] << 8)) + off) & 4095;
                m |= (1ull << (a & 15))
                   | (1ull << (16 + ((a >> 4) & 15)))
                   | (1ull << (32 + ((a >> 8) & 15)));
            }
        }
        out[i] = m;
    }

    // vectorized mask store (64B per thread, contiguous)
    ulonglong2* gm2 = reinterpret_cast<ulonglong2*>(&g_mask[b * SS + base]);
#pragma unroll
    for (int k = 0; k < 4; k++)
        gm2[k] = make_ulonglong2(out[2 * k], out[2 * k + 1]);
}

// ---------------------------------------------------------------------------
// Kernel 2: pure streaming gather + masked overwrite. 4 tokens per thread.
// ---------------------------------------------------------------------------
__device__ __forceinline__ void apply_mask(float4& v, u64 m, int tid) {
    if (tid >= 51 && tid <= 63) {
        int d0 = tid << 2;
        float* vp = reinterpret_cast<float*>(&v);
#pragma unroll
        for (int c = 0; c < 4; c++) {
            int d = d0 + c;
            if (d >= 206 && d < 254 && ((m >> (d - 206)) & 1ull)) vp[c] = 1.0f;
        }
    } else if (tid == 114) {
        if ((m >> 48) & 1ull) v.x = 1.0f;   // dim 456
        if ((m >> 49) & 1ull) v.y = 1.0f;   // dim 457
        if ((m >> 50) & 1ull) v.z = 1.0f;   // dim 458
    }
}

__global__ void __launch_bounds__(256) nvm_embed_kernel(
    const float4* __restrict__ tbl4,          // [272 * 128]
    float4* __restrict__ out4)                // [NTOK * 128]
{
    int tid  = threadIdx.x;                   // 0..127 (dim lane)
    int slot = threadIdx.y;                   // 0..1
    int base = blockIdx.x * 8 + slot * 4;     // 4 consecutive tokens

    ulonglong2 ma = *reinterpret_cast<const ulonglong2*>(&g_mask[base]);
    ulonglong2 mb = *reinterpret_cast<const ulonglong2*>(&g_mask[base + 2]);
    u64 m[4] = {ma.x, ma.y, mb.x, mb.y};

    float4 v[4];
#pragma unroll
    for (int k = 0; k < 4; k++) {
        int t = (int)((m[k] >> 52) & 511);
        v[k] = __ldg(&tbl4[t * 128 + tid]);
    }
#pragma unroll
    for (int k = 0; k < 4; k++) apply_mask(v[k], m[k], tid);
#pragma unroll
    for (int k = 0; k < 4; k++)
        __stcs(&out4[(size_t)(base + k) * 128 + tid], v[k]);
}

// ---------------------------------------------------------------------------
extern "C" void kernel_launch(void* const* d_in, const int* in_sizes, int n_in,
                              void* d_out, int out_size) {
    const float* tbl;
    const int* tok;
    if (in_sizes[0] == 272 * 512) {
        tbl = (const float*)d_in[0];
        tok = (const int*)d_in[1];
    } else {
        tbl = (const float*)d_in[1];
        tok = (const int*)d_in[0];
    }
    float* out = (float*)d_out;

    nvm_scan_kernel<<<BB, 1024>>>(tok);

    dim3 blk(128, 2);
    nvm_embed_kernel<<<NTOK / 8, blk>>>((const float4*)tbl, (float4*)out);
}

// round 4
// speedup vs baseline: 1.5441x; 1.0218x over previous
#include <cuda_runtime.h>
#include <cstdint>

#define BB 8
#define SS 8192
#define NTOK (BB * SS)
#define TPB_TOK 8          // tokens per block in embed kernel

typedef unsigned long long u64;

// Per-token packed word:
//   bits [0,48)  : addr one-hot (lo/hi/top nibbles)
//   bit 48       : THINK_START  -> dim 456
//   bit 49       : THINK_END    -> dim 457
//   bit 50       : MEM_EXEC     -> dim 458
//   bits [52,61) : token id (0..271)
__device__ u64 g_mask[NTOK];

// ---------------------------------------------------------------------------
// Kernel 1: per-row scan + full per-token mask computation.
// One block per batch row, 1024 threads, 8 contiguous tokens per thread.
// ---------------------------------------------------------------------------
__global__ void __launch_bounds__(1024) nvm_scan_kernel(const int* __restrict__ tok) {
    __shared__ int sh[SS];           // 32 KB
    __shared__ int warp_part[32];
    __shared__ int ce_sh;

    int b = blockIdx.x;
    int tid = threadIdx.x;
    int lane = tid & 31;
    int wid = tid >> 5;

    if (tid == 0) ce_sh = SS;

    const int4* row4 = reinterpret_cast<const int4*>(tok + b * SS);
    int4* sh4 = reinterpret_cast<int4*>(sh);
#pragma unroll
    for (int i = tid; i < SS / 4; i += 1024) sh4[i] = row4[i];
    __syncthreads();

    int base = tid * 8;

    // win[0..7] = predecessor thread's 8 tokens, win[8..15] = own 8 tokens
    int win[16];
    {
        int4 a, c;
        if (tid > 0) {
            a = sh4[tid * 2 - 2];
            c = sh4[tid * 2 - 1];
        } else {
            a = make_int4(0, 0, 0, 0);
            c = a;
        }
        win[0] = a.x; win[1] = a.y; win[2] = a.z; win[3] = a.w;
        win[4] = c.x; win[5] = c.y; win[6] = c.z; win[7] = c.w;
        int4 d = sh4[tid * 2];
        int4 e = sh4[tid * 2 + 1];
        win[8]  = d.x; win[9]  = d.y; win[10] = d.z; win[11] = d.w;
        win[12] = e.x; win[13] = e.y; win[14] = e.z; win[15] = e.w;
    }

    int vals[8];
    int run = -1, lce = SS;
#pragma unroll
    for (int i = 0; i < 8; i++) {
        int t = win[8 + i];
        if (t == 256) run = base + i;
        vals[i] = run;
        if (t == 257 && (base + i) < lce) lce = base + i;
    }
    if (lce < SS) atomicMin(&ce_sh, lce);

    // warp-shuffle inclusive max-scan of per-thread `run`
    int v = run;
#pragma unroll
    for (int off = 1; off < 32; off <<= 1) {
        int o = __shfl_up_sync(0xffffffffu, v, off);
        if (lane >= off && o > v) v = o;
    }
    if (lane == 31) warp_part[wid] = v;
    __syncthreads();
    if (wid == 0) {
        int w = warp_part[lane];
#pragma unroll
        for (int off = 1; off < 32; off <<= 1) {
            int o = __shfl_up_sync(0xffffffffu, w, off);
            if (lane >= off && o > w) w = o;
        }
        warp_part[lane] = w;
    }
    __syncthreads();

    int warp_prefix = (wid == 0) ? -1 : warp_part[wid - 1];
    int excl_in_warp = __shfl_up_sync(0xffffffffu, v, 1);
    if (lane == 0) excl_in_warp = -1;
    int prefix = (excl_in_warp > warp_prefix) ? excl_in_warp : warp_prefix;
    int fce = ce_sh;

    u64 out[8];
#pragma unroll
    for (int i = 0; i < 8; i++) {
        int s = base + i;
        int t = win[8 + i];
        int cs = (vals[i] > prefix) ? vals[i] : prefix;

        u64 m = ((u64)t) << 52;
        if (t == 259) m |= (1ull << 48);
        if (t == 260) m |= (1ull << 49);
        if (t == 258 && (s + 8) < SS) m |= (1ull << 50);

        // code path
        if (cs >= 0 && s < fce && t < 256) {
            int seq = s - cs - 1;
            int bo  = seq & 7;
            if (seq >= 0 && bo < 5) {
                int addr = (((seq >> 3) << 3) + 2 + bo) & 4095;
                m |= (1ull << (addr & 15))
                   | (1ull << (16 + ((addr >> 4) & 15)))
                   | (1ull << (32 + ((addr >> 8) & 15)));
            }
        }
        // mem look-back: source position jg = s - 5 - off, window idx ji = i+3-off
#pragma unroll
        for (int off = 0; off < 4; off++) {
            int jg = s - 5 - off;
            int ji = i + 3 - off;
            if (jg >= 0 && (jg + 8) < SS && win[ji] == 258) {
                int a = ((win[ji + 1] | (win[ji + 2] << 8)) + off) & 4095;
                m |= (1ull << (a & 15))
                   | (1ull << (16 + ((a >> 4) & 15)))
                   | (1ull << (32 + ((a >> 8) & 15)));
            }
        }
        out[i] = m;
    }

    ulonglong2* gm2 = reinterpret_cast<ulonglong2*>(&g_mask[b * SS + base]);
#pragma unroll
    for (int k = 0; k < 4; k++)
        gm2[k] = make_ulonglong2(out[2 * k], out[2 * k + 1]);
}

// ---------------------------------------------------------------------------
// Kernel 2: gather into SMEM tile, bulk-async store tile to GMEM.
// 256 threads, 8 tokens/block, 4 token-float4s per thread.
// ---------------------------------------------------------------------------
__device__ __forceinline__ void apply_mask(float4& v, u64 m, int lane) {
    if (lane >= 51 && lane <= 63) {
        int d0 = lane << 2;
        float* vp = reinterpret_cast<float*>(&v);
#pragma unroll
        for (int c = 0; c < 4; c++) {
            int d = d0 + c;
            if (d >= 206 && d < 254 && ((m >> (d - 206)) & 1ull)) vp[c] = 1.0f;
        }
    } else if (lane == 114) {
        if ((m >> 48) & 1ull) v.x = 1.0f;   // dim 456
        if ((m >> 49) & 1ull) v.y = 1.0f;   // dim 457
        if ((m >> 50) & 1ull) v.z = 1.0f;   // dim 458
    }
}

__global__ void __launch_bounds__(256) nvm_embed_kernel(
    const float4* __restrict__ tbl4,          // [272 * 128]
    float4* __restrict__ out4)                // [NTOK * 128]
{
    __shared__ alignas(128) float4 buf[TPB_TOK * 128];   // 16 KiB

    int tid  = threadIdx.x;
    int lane = tid & 127;            // dim lane (float4 index)
    int grp  = tid >> 7;             // 0..1
    int base = blockIdx.x * TPB_TOK;

    // 4 tokens per thread: local indices grp, grp+2, grp+4, grp+6
    u64 m[4];
#pragma unroll
    for (int k = 0; k < 4; k++)
        m[k] = __ldg(&g_mask[base + grp + 2 * k]);   // warp-broadcast loads

    float4 v[4];
#pragma unroll
    for (int k = 0; k < 4; k++) {
        int t = (int)((m[k] >> 52) & 511);
        v[k] = __ldg(&tbl4[t * 128 + lane]);
    }
#pragma unroll
    for (int k = 0; k < 4; k++) apply_mask(v[k], m[k], lane);
#pragma unroll
    for (int k = 0; k < 4; k++)
        buf[(grp + 2 * k) * 128 + lane] = v[k];

    __syncthreads();

    if (tid == 0) {
        asm volatile("fence.proxy.async.shared::cta;" ::: "memory");
        unsigned int saddr = (unsigned int)__cvta_generic_to_shared(buf);
        unsigned long long gaddr =
            (unsigned long long)(out4 + (size_t)base * 128);
        asm volatile(
            "cp.async.bulk.global.shared::cta.bulk_group [%0], [%1], %2;"
            :: "l"(gaddr), "r"(saddr), "r"(TPB_TOK * 128 * 16)
            : "memory");
        asm volatile("cp.async.bulk.commit_group;" ::: "memory");
        asm volatile("cp.async.bulk.wait_group.read 0;" ::: "memory");
    }
}

// ---------------------------------------------------------------------------
extern "C" void kernel_launch(void* const* d_in, const int* in_sizes, int n_in,
                              void* d_out, int out_size) {
    const float* tbl;
    const int* tok;
    if (in_sizes[0] == 272 * 512) {
        tbl = (const float*)d_in[0];
        tok = (const int*)d_in[1];
    } else {
        tbl = (const float*)d_in[1];
        tok = (const int*)d_in[0];
    }
    float* out = (float*)d_out;

    nvm_scan_kernel<<<BB, 1024>>>(tok);
    nvm_embed_kernel<<<NTOK / TPB_TOK, 256>>>((const float4*)tbl, (float4*)out);
}